// round 1
// baseline (speedup 1.0000x reference)
#include <cuda_runtime.h>

// ============================================================================
// LigandEncoder (3-layer GIN + global_add_pool)
//   per layer: agg = h + scatter_add(h[src] -> dst)
//              h   = relu( relu(agg@W1 + b1) @ W2 + b2 )
//   out = segment_sum(h, batch)  -> (512, 128) fp32
// ============================================================================

#define DIMF 128
typedef unsigned long long ull;

// Scratch (allocation-free rule: __device__ globals). 100000 * 128 floats each.
#define MAXN 100000
__device__ float g_agg[(size_t)MAXN * DIMF];
__device__ float g_tmp[(size_t)MAXN * DIMF];
__device__ float g_h  [(size_t)MAXN * DIMF];

// ---------------------------------------------------------------------------
// helpers
// ---------------------------------------------------------------------------
__device__ __forceinline__ ull ffma2(ull a, ull b, ull c) {
    ull d;
    asm("fma.rn.f32x2 %0, %1, %2, %3;" : "=l"(d) : "l"(a), "l"(b), "l"(c));
    return d;
}
__device__ __forceinline__ ull dup_f(float v) {
    unsigned u = __float_as_uint(v);
    return ((ull)u << 32) | (ull)u;
}
__device__ __forceinline__ float lo_f(ull x) { return __uint_as_float((unsigned)x); }
__device__ __forceinline__ float hi_f(ull x) { return __uint_as_float((unsigned)(x >> 32)); }

__device__ __forceinline__ void red_add_v4(const float* p, float4 v) {
    asm volatile("red.global.add.v4.f32 [%0], {%1,%2,%3,%4};"
                 :: "l"(p), "f"(v.x), "f"(v.y), "f"(v.z), "f"(v.w)
                 : "memory");
}

// ---------------------------------------------------------------------------
// copy h -> agg  (folds the "+h" self term; vectorized)
// ---------------------------------------------------------------------------
__global__ void copy_kernel(const float4* __restrict__ src, float4* __restrict__ dst, int n4) {
    int i = blockIdx.x * blockDim.x + threadIdx.x;
    if (i < n4) dst[i] = src[i];
}

__global__ void zero_kernel(float4* __restrict__ p, int n4) {
    int i = blockIdx.x * blockDim.x + threadIdx.x;
    if (i < n4) p[i] = make_float4(0.f, 0.f, 0.f, 0.f);
}

// ---------------------------------------------------------------------------
// edge scatter: one warp per edge; lane l handles floats [4l, 4l+4)
// ---------------------------------------------------------------------------
__global__ void scatter_kernel(const float* __restrict__ h,
                               const int* __restrict__ src,
                               const int* __restrict__ dst,
                               float* __restrict__ agg, int E) {
    int idx  = blockIdx.x * blockDim.x + threadIdx.x;
    int e    = idx >> 5;
    int lane = idx & 31;
    if (e >= E) return;
    int s = __ldg(src + e);
    int d = __ldg(dst + e);
    float4 v = __ldg(((const float4*)(h + (size_t)s * DIMF)) + lane);
    red_add_v4(agg + (size_t)d * DIMF + lane * 4, v);
}

// ---------------------------------------------------------------------------
// global_add_pool: one warp per node, reduce into out[batch[node]]
// ---------------------------------------------------------------------------
__global__ void pool_kernel(const float* __restrict__ h,
                            const int* __restrict__ batch,
                            float* __restrict__ out, int M) {
    int idx  = blockIdx.x * blockDim.x + threadIdx.x;
    int node = idx >> 5;
    int lane = idx & 31;
    if (node >= M) return;
    int g = __ldg(batch + node);
    float4 v = __ldg(((const float4*)(h + (size_t)node * DIMF)) + lane);
    red_add_v4(out + (size_t)g * DIMF + lane * 4, v);
}

// ---------------------------------------------------------------------------
// C = relu(A @ W + b), A:(M,128), W:(128,128), all fp32.
// Tile: 64 rows x 128 cols per block, 256 threads (16x16),
// thread micro-tile 4 rows x 8 cols as 4x4 packed f32x2 accumulators.
// W resident in SMEM (64 KB); A staged in 32-wide K chunks, each value stored
// PRE-DUPLICATED as (a,a) 64-bit so the inner loop is LDS.64 + FFMA2 only.
// Dynamic SMEM: 64 KB (W) + 16 KB (A-dup) = 80 KB -> 2 blocks/SM.
// ---------------------------------------------------------------------------
__global__ __launch_bounds__(256, 2)
void gemm_bias_relu(const float* __restrict__ A, const float* __restrict__ W,
                    const float* __restrict__ bias, float* __restrict__ C, int M) {
    extern __shared__ char smem_raw[];
    float* sW = (float*)smem_raw;                       // [128][128]
    ull*   sA = (ull*)(smem_raw + DIMF * DIMF * 4);     // [32][64] duplicated pairs

    const int tid = threadIdx.x;
    const int tx  = tid & 15;    // col group: cols [8*tx, 8*tx+8)
    const int ty  = tid >> 4;    // row group: rows [4*ty, 4*ty+4)
    const int row0 = blockIdx.x * 64;

    // Load W: 16384 floats = 4096 float4, 256 threads x 16
    {
        const float4* Wg  = (const float4*)W;
        float4*       Ws4 = (float4*)sW;
#pragma unroll
        for (int i = 0; i < 16; i++) Ws4[tid + i * 256] = __ldg(Wg + tid + i * 256);
    }

    ull acc[4][4];
#pragma unroll
    for (int i = 0; i < 4; i++)
#pragma unroll
        for (int j = 0; j < 4; j++) acc[i][j] = 0ull;

    for (int kk = 0; kk < DIMF; kk += 32) {
        // stage A chunk: 64 rows x 32 k = 512 float4 slots, 2 per thread
        float4 v[2];
        int rr[2], kc[2];
#pragma unroll
        for (int j = 0; j < 2; j++) {
            int s = tid + j * 256;        // 0..511
            rr[j] = s >> 3;               // row in tile
            kc[j] = s & 7;                // float4 index in chunk
            int grow = row0 + rr[j];
            if (grow < M)
                v[j] = __ldg(((const float4*)(A + (size_t)grow * DIMF + kk)) + kc[j]);
            else
                v[j] = make_float4(0.f, 0.f, 0.f, 0.f);
        }
        __syncthreads();   // previous chunk fully consumed
#pragma unroll
        for (int j = 0; j < 2; j++) {
            int kb = kc[j] * 4;
            sA[(kb + 0) * 64 + rr[j]] = dup_f(v[j].x);
            sA[(kb + 1) * 64 + rr[j]] = dup_f(v[j].y);
            sA[(kb + 2) * 64 + rr[j]] = dup_f(v[j].z);
            sA[(kb + 3) * 64 + rr[j]] = dup_f(v[j].w);
        }
        __syncthreads();

#pragma unroll
        for (int k = 0; k < 32; k++) {
            ull a0 = sA[k * 64 + ty * 4 + 0];
            ull a1 = sA[k * 64 + ty * 4 + 1];
            ull a2 = sA[k * 64 + ty * 4 + 2];
            ull a3 = sA[k * 64 + ty * 4 + 3];
            const ull* wp = (const ull*)(sW + (kk + k) * DIMF + tx * 8);
            ull b0 = wp[0], b1 = wp[1], b2 = wp[2], b3 = wp[3];
            acc[0][0] = ffma2(a0, b0, acc[0][0]);
            acc[0][1] = ffma2(a0, b1, acc[0][1]);
            acc[0][2] = ffma2(a0, b2, acc[0][2]);
            acc[0][3] = ffma2(a0, b3, acc[0][3]);
            acc[1][0] = ffma2(a1, b0, acc[1][0]);
            acc[1][1] = ffma2(a1, b1, acc[1][1]);
            acc[1][2] = ffma2(a1, b2, acc[1][2]);
            acc[1][3] = ffma2(a1, b3, acc[1][3]);
            acc[2][0] = ffma2(a2, b0, acc[2][0]);
            acc[2][1] = ffma2(a2, b1, acc[2][1]);
            acc[2][2] = ffma2(a2, b2, acc[2][2]);
            acc[2][3] = ffma2(a2, b3, acc[2][3]);
            acc[3][0] = ffma2(a3, b0, acc[3][0]);
            acc[3][1] = ffma2(a3, b1, acc[3][1]);
            acc[3][2] = ffma2(a3, b2, acc[3][2]);
            acc[3][3] = ffma2(a3, b3, acc[3][3]);
        }
    }

    // epilogue: + bias, relu, vectorized store
    float4 bv0 = __ldg(((const float4*)(bias + tx * 8)));
    float4 bv1 = __ldg(((const float4*)(bias + tx * 8)) + 1);
#pragma unroll
    for (int i = 0; i < 4; i++) {
        int row = row0 + ty * 4 + i;
        if (row < M) {
            float4 o0, o1;
            o0.x = fmaxf(lo_f(acc[i][0]) + bv0.x, 0.f);
            o0.y = fmaxf(hi_f(acc[i][0]) + bv0.y, 0.f);
            o0.z = fmaxf(lo_f(acc[i][1]) + bv0.z, 0.f);
            o0.w = fmaxf(hi_f(acc[i][1]) + bv0.w, 0.f);
            o1.x = fmaxf(lo_f(acc[i][2]) + bv1.x, 0.f);
            o1.y = fmaxf(hi_f(acc[i][2]) + bv1.y, 0.f);
            o1.z = fmaxf(lo_f(acc[i][3]) + bv1.z, 0.f);
            o1.w = fmaxf(hi_f(acc[i][3]) + bv1.w, 0.f);
            float4* cp = (float4*)(C + (size_t)row * DIMF + tx * 8);
            cp[0] = o0;
            cp[1] = o1;
        }
    }
}

// ---------------------------------------------------------------------------
// launch
// ---------------------------------------------------------------------------
extern "C" void kernel_launch(void* const* d_in, const int* in_sizes, int n_in,
                              void* d_out, int out_size) {
    const float* x     = (const float*)d_in[0];
    const int*   ei    = (const int*)d_in[1];
    const int*   batch = (const int*)d_in[2];
    const int E = in_sizes[1] / 2;
    const int M = in_sizes[2];          // number of nodes
    const int* src = ei;
    const int* dst = ei + E;

    void *p_agg, *p_tmp, *p_h;
    cudaGetSymbolAddress(&p_agg, g_agg);
    cudaGetSymbolAddress(&p_tmp, g_tmp);
    cudaGetSymbolAddress(&p_h,   g_h);
    float* agg = (float*)p_agg;
    float* tmp = (float*)p_tmp;
    float* hbf = (float*)p_h;

    const int SMEM_GEMM = DIMF * DIMF * 4 + 32 * 64 * 8;   // 80 KB
    cudaFuncSetAttribute(gemm_bias_relu,
                         cudaFuncAttributeMaxDynamicSharedMemorySize, SMEM_GEMM);

    const int n4      = M * DIMF / 4;
    const int cpBlocks  = (n4 + 255) / 256;
    const int scBlocks  = (E * 32 + 255) / 256;
    const int poBlocks  = (M * 32 + 255) / 256;
    const int gmBlocks  = (M + 63) / 64;

    const float* h = x;
    for (int l = 0; l < 3; l++) {
        const float* W1 = (const float*)d_in[3 + 4 * l + 0];
        const float* b1 = (const float*)d_in[3 + 4 * l + 1];
        const float* W2 = (const float*)d_in[3 + 4 * l + 2];
        const float* b2 = (const float*)d_in[3 + 4 * l + 3];

        copy_kernel<<<cpBlocks, 256>>>((const float4*)h, (float4*)agg, n4);
        scatter_kernel<<<scBlocks, 256>>>(h, src, dst, agg, E);
        gemm_bias_relu<<<gmBlocks, 256, SMEM_GEMM>>>(agg, W1, b1, tmp, M);
        gemm_bias_relu<<<gmBlocks, 256, SMEM_GEMM>>>(tmp, W2, b2, hbf, M);
        h = hbf;
    }

    zero_kernel<<<(out_size / 4 + 255) / 256, 256>>>((float4*)d_out, out_size / 4);
    pool_kernel<<<poBlocks, 256>>>(h, batch, (float*)d_out, M);
}

// round 3
// speedup vs baseline: 1.3287x; 1.3287x over previous
#include <cuda_runtime.h>

// ============================================================================
// LigandEncoder (3-layer GIN + global_add_pool)
//   per layer: agg = h + scatter_add(h[src] -> dst)
//              h   = relu( relu(agg@W1 + b1) @ W2 + b2 )
//   out = segment_sum(h, batch)  -> (512, 128) fp32
// ============================================================================

#define DIMF 128
typedef unsigned long long ull;

// Scratch (allocation-free rule: __device__ globals). 100000 * 128 floats each.
#define MAXN 100000
__device__ float g_agg[(size_t)MAXN * DIMF];
__device__ float g_tmp[(size_t)MAXN * DIMF];
__device__ float g_h  [(size_t)MAXN * DIMF];

// ---------------------------------------------------------------------------
// helpers
// ---------------------------------------------------------------------------
__device__ __forceinline__ ull ffma2(ull a, ull b, ull c) {
    ull d;
    asm("fma.rn.f32x2 %0, %1, %2, %3;" : "=l"(d) : "l"(a), "l"(b), "l"(c));
    return d;
}
__device__ __forceinline__ ull dup_f(float v) {
    unsigned u = __float_as_uint(v);
    return ((ull)u << 32) | (ull)u;
}
__device__ __forceinline__ ull pack2(float lo, float hi) {
    return ((ull)__float_as_uint(hi) << 32) | (ull)__float_as_uint(lo);
}
__device__ __forceinline__ float lo_f(ull x) { return __uint_as_float((unsigned)x); }
__device__ __forceinline__ float hi_f(ull x) { return __uint_as_float((unsigned)(x >> 32)); }

__device__ __forceinline__ void red_add_v4(const float* p, float4 v) {
    asm volatile("red.global.add.v4.f32 [%0], {%1,%2,%3,%4};"
                 :: "l"(p), "f"(v.x), "f"(v.y), "f"(v.z), "f"(v.w)
                 : "memory");
}

// ---------------------------------------------------------------------------
// copy h -> agg  (folds the "+h" self term; vectorized)
// ---------------------------------------------------------------------------
__global__ void copy_kernel(const float4* __restrict__ src, float4* __restrict__ dst, int n4) {
    int i = blockIdx.x * blockDim.x + threadIdx.x;
    if (i < n4) dst[i] = src[i];
}

__global__ void zero_kernel(float4* __restrict__ p, int n4) {
    int i = blockIdx.x * blockDim.x + threadIdx.x;
    if (i < n4) p[i] = make_float4(0.f, 0.f, 0.f, 0.f);
}

// ---------------------------------------------------------------------------
// edge scatter: one warp per edge; lane l handles floats [4l, 4l+4)
// ---------------------------------------------------------------------------
__global__ void scatter_kernel(const float* __restrict__ h,
                               const int* __restrict__ src,
                               const int* __restrict__ dst,
                               float* __restrict__ agg, int E) {
    int idx  = blockIdx.x * blockDim.x + threadIdx.x;
    int e    = idx >> 5;
    int lane = idx & 31;
    if (e >= E) return;
    int s = __ldg(src + e);
    int d = __ldg(dst + e);
    float4 v = __ldg(((const float4*)(h + (size_t)s * DIMF)) + lane);
    red_add_v4(agg + (size_t)d * DIMF + lane * 4, v);
}

// ---------------------------------------------------------------------------
// global_add_pool: one warp per node, reduce into out[batch[node]]
// ---------------------------------------------------------------------------
__global__ void pool_kernel(const float* __restrict__ h,
                            const int* __restrict__ batch,
                            float* __restrict__ out, int M) {
    int idx  = blockIdx.x * blockDim.x + threadIdx.x;
    int node = idx >> 5;
    int lane = idx & 31;
    if (node >= M) return;
    int g = __ldg(batch + node);
    float4 v = __ldg(((const float4*)(h + (size_t)node * DIMF)) + lane);
    red_add_v4(out + (size_t)g * DIMF + lane * 4, v);
}

// ---------------------------------------------------------------------------
// C = relu(A @ W + b), A:(M,128), W:(128,128), fp32 via packed f32x2 FFMA.
//
// Block tile: 128 rows x 128 cols, 256 threads. tx = tid&7 (col phase),
// ty = tid>>3 (row group). Thread micro-tile: 4 rows x 16 cols held as
// 4x8 packed-f32x2 accumulators; thread's ull-columns are tx + 8j (strided),
// so a warp's W reads are 8 distinct consecutive 8B words -> conflict-free
// (1 phase + broadcast). A is staged per 32-k chunk as PRE-DUPLICATED (a,a)
// pairs in sA[k][row] (stride 129 ull for staging-store conflicts); inner-loop
// A reads are 4-address broadcasts.
// Per-SM per k (2 blocks): smem phases ~192 cyc vs FFMA2 issue ~256 cyc
// -> FMA-bound. Floor ~45us/GEMM.
// Dynamic smem: 64KB (W) + 33KB (A-dup) = 96.25KB -> 2 blocks/SM.
// ---------------------------------------------------------------------------
#define SA_STRIDE 129
__global__ __launch_bounds__(256, 2)
void gemm_bias_relu(const float* __restrict__ A, const float* __restrict__ W,
                    const float* __restrict__ bias, float* __restrict__ C, int M) {
    extern __shared__ char smem_raw[];
    float* sW = (float*)smem_raw;                       // [128][128] floats
    ull*   sA = (ull*)(smem_raw + DIMF * DIMF * 4);     // [32][SA_STRIDE] dup pairs

    const int tid = threadIdx.x;
    const int tx  = tid & 7;     // ull-col phase: cols tx + 8j, j=0..7
    const int ty  = tid >> 3;    // row group: rows [4*ty, 4*ty+4)
    const int row0 = blockIdx.x * 128;

    // Load W: 16384 floats = 4096 float4, 256 threads x 16
    {
        const float4* Wg  = (const float4*)W;
        float4*       Ws4 = (float4*)sW;
#pragma unroll
        for (int i = 0; i < 16; i++) Ws4[tid + i * 256] = __ldg(Wg + tid + i * 256);
    }
    const ull* sWu = (const ull*)sW;   // [128][64] ull view

    ull acc[4][8];
#pragma unroll
    for (int i = 0; i < 4; i++)
#pragma unroll
        for (int j = 0; j < 8; j++) acc[i][j] = 0ull;

#pragma unroll 1
    for (int kk = 0; kk < DIMF; kk += 32) {
        // stage A chunk: 128 rows x 32 k = 1024 float4 slots, 4 per thread
        float4 v[4];
        int rr[4], kc[4];
#pragma unroll
        for (int j = 0; j < 4; j++) {
            int s = tid + j * 256;        // 0..1023
            rr[j] = s >> 3;               // row in tile (0..127)
            kc[j] = s & 7;                // float4 index in chunk (0..7)
            int grow = row0 + rr[j];
            if (grow < M)
                v[j] = __ldg(((const float4*)(A + (size_t)grow * DIMF + kk)) + kc[j]);
            else
                v[j] = make_float4(0.f, 0.f, 0.f, 0.f);
        }
        __syncthreads();   // previous chunk fully consumed
#pragma unroll
        for (int j = 0; j < 4; j++) {
            int kb = kc[j] * 4;
            sA[(kb + 0) * SA_STRIDE + rr[j]] = dup_f(v[j].x);
            sA[(kb + 1) * SA_STRIDE + rr[j]] = dup_f(v[j].y);
            sA[(kb + 2) * SA_STRIDE + rr[j]] = dup_f(v[j].z);
            sA[(kb + 3) * SA_STRIDE + rr[j]] = dup_f(v[j].w);
        }
        __syncthreads();

#pragma unroll 8
        for (int k = 0; k < 32; k++) {
            ull a[4], b[8];
#pragma unroll
            for (int i = 0; i < 4; i++) a[i] = sA[k * SA_STRIDE + ty * 4 + i];
#pragma unroll
            for (int j = 0; j < 8; j++) b[j] = sWu[(kk + k) * 64 + tx + 8 * j];
#pragma unroll
            for (int i = 0; i < 4; i++)
#pragma unroll
                for (int j = 0; j < 8; j++)
                    acc[i][j] = ffma2(a[i], b[j], acc[i][j]);
        }
    }

    // epilogue: + bias, relu, STG.64 per (row, col-pair)
    const ull* bu = (const ull*)bias;   // pairs (b[2c], b[2c+1])
    ull bv[8];
#pragma unroll
    for (int j = 0; j < 8; j++) bv[j] = __ldg(bu + tx + 8 * j);

#pragma unroll
    for (int i = 0; i < 4; i++) {
        int row = row0 + ty * 4 + i;
        if (row < M) {
            ull* cp = (ull*)(C + (size_t)row * DIMF);
#pragma unroll
            for (int j = 0; j < 8; j++) {
                float lo = fmaxf(lo_f(acc[i][j]) + lo_f(bv[j]), 0.f);
                float hi = fmaxf(hi_f(acc[i][j]) + hi_f(bv[j]), 0.f);
                cp[tx + 8 * j] = pack2(lo, hi);
            }
        }
    }
}

// ---------------------------------------------------------------------------
// launch
// ---------------------------------------------------------------------------
extern "C" void kernel_launch(void* const* d_in, const int* in_sizes, int n_in,
                              void* d_out, int out_size) {
    const float* x     = (const float*)d_in[0];
    const int*   ei    = (const int*)d_in[1];
    const int*   batch = (const int*)d_in[2];
    const int E = in_sizes[1] / 2;
    const int M = in_sizes[2];          // number of nodes
    const int* src = ei;
    const int* dst = ei + E;

    void *p_agg, *p_tmp, *p_h;
    cudaGetSymbolAddress(&p_agg, g_agg);
    cudaGetSymbolAddress(&p_tmp, g_tmp);
    cudaGetSymbolAddress(&p_h,   g_h);
    float* agg = (float*)p_agg;
    float* tmp = (float*)p_tmp;
    float* hbf = (float*)p_h;

    const int SMEM_GEMM = DIMF * DIMF * 4 + 32 * SA_STRIDE * 8;   // 96.25 KB
    cudaFuncSetAttribute(gemm_bias_relu,
                         cudaFuncAttributeMaxDynamicSharedMemorySize, SMEM_GEMM);

    const int n4       = M * DIMF / 4;
    const int cpBlocks = (n4 + 255) / 256;
    const int scBlocks = (E * 32 + 255) / 256;
    const int poBlocks = (M * 32 + 255) / 256;
    const int gmBlocks = (M + 127) / 128;

    const float* h = x;
    for (int l = 0; l < 3; l++) {
        const float* W1 = (const float*)d_in[3 + 4 * l + 0];
        const float* b1 = (const float*)d_in[3 + 4 * l + 1];
        const float* W2 = (const float*)d_in[3 + 4 * l + 2];
        const float* b2 = (const float*)d_in[3 + 4 * l + 3];

        copy_kernel<<<cpBlocks, 256>>>((const float4*)h, (float4*)agg, n4);
        scatter_kernel<<<scBlocks, 256>>>(h, src, dst, agg, E);
        gemm_bias_relu<<<gmBlocks, 256, SMEM_GEMM>>>(agg, W1, b1, tmp, M);
        gemm_bias_relu<<<gmBlocks, 256, SMEM_GEMM>>>(tmp, W2, b2, hbf, M);
        h = hbf;
    }

    zero_kernel<<<(out_size / 4 + 255) / 256, 256>>>((float4*)d_out, out_size / 4);
    pool_kernel<<<poBlocks, 256>>>(h, batch, (float*)d_out, M);
}

// round 4
// speedup vs baseline: 1.9800x; 1.4901x over previous
#include <cuda_runtime.h>

// ============================================================================
// LigandEncoder (3-layer GIN + global_add_pool)
//   CSR build (once):   deg hist -> scan -> fill   (graph is static per call)
//   per layer: agg[d] = h[d] + sum_{s in nbr(d)} h[s]     (gather, no atomics)
//              h      = relu( relu(agg@W1 + b1) @ W2 + b2 )
//   out = segment_sum(h, batch)  -> (512, 128) fp32
// ============================================================================

#define DIMF 128
typedef unsigned long long ull;

#define MAXN 100000
#define MAXE 1600000
#define SCAN_BS 1024

// Scratch (allocation-free rule: __device__ globals).
__device__ float g_agg[(size_t)MAXN * DIMF];
__device__ float g_tmp[(size_t)MAXN * DIMF];
__device__ float g_h  [(size_t)MAXN * DIMF];
__device__ int   g_deg[MAXN];
__device__ int   g_rowptr[MAXN];
__device__ int   g_cursor[MAXN];
__device__ int   g_csr[MAXE];
__device__ int   g_part[(MAXN + SCAN_BS - 1) / SCAN_BS + 1];

// ---------------------------------------------------------------------------
// helpers
// ---------------------------------------------------------------------------
__device__ __forceinline__ ull ffma2(ull a, ull b, ull c) {
    ull d;
    asm("fma.rn.f32x2 %0, %1, %2, %3;" : "=l"(d) : "l"(a), "l"(b), "l"(c));
    return d;
}
__device__ __forceinline__ ull dup_f(float v) {
    unsigned u = __float_as_uint(v);
    return ((ull)u << 32) | (ull)u;
}
__device__ __forceinline__ ull pack2(float lo, float hi) {
    return ((ull)__float_as_uint(hi) << 32) | (ull)__float_as_uint(lo);
}
__device__ __forceinline__ float lo_f(ull x) { return __uint_as_float((unsigned)x); }
__device__ __forceinline__ float hi_f(ull x) { return __uint_as_float((unsigned)(x >> 32)); }

__device__ __forceinline__ void red_add_v4(const float* p, float4 v) {
    asm volatile("red.global.add.v4.f32 [%0], {%1,%2,%3,%4};"
                 :: "l"(p), "f"(v.x), "f"(v.y), "f"(v.z), "f"(v.w)
                 : "memory");
}

// ---------------------------------------------------------------------------
// CSR build kernels
// ---------------------------------------------------------------------------
__global__ void zero_int_kernel(int* __restrict__ p, int n) {
    int i = blockIdx.x * blockDim.x + threadIdx.x;
    if (i < n) p[i] = 0;
}

__global__ void hist_kernel(const int* __restrict__ dst, int* __restrict__ deg, int E) {
    int e = blockIdx.x * blockDim.x + threadIdx.x;
    if (e < E) atomicAdd(deg + __ldg(dst + e), 1);
}

// per-block exclusive scan (Hillis-Steele), block total -> part[b]
__global__ void scan_block_kernel(const int* __restrict__ deg, int* __restrict__ rowptr,
                                  int* __restrict__ part, int M) {
    __shared__ int sh[SCAN_BS];
    int i = blockIdx.x * SCAN_BS + threadIdx.x;
    int v = (i < M) ? deg[i] : 0;
    sh[threadIdx.x] = v;
    __syncthreads();
#pragma unroll
    for (int off = 1; off < SCAN_BS; off <<= 1) {
        int t = (threadIdx.x >= off) ? sh[threadIdx.x - off] : 0;
        __syncthreads();
        sh[threadIdx.x] += t;
        __syncthreads();
    }
    if (i < M) rowptr[i] = sh[threadIdx.x] - v;   // exclusive
    if (threadIdx.x == SCAN_BS - 1) part[blockIdx.x] = sh[SCAN_BS - 1];
}

__global__ void scan_part_kernel(int* __restrict__ part, int nb) {
    if (threadIdx.x == 0 && blockIdx.x == 0) {
        int acc = 0;
        for (int b = 0; b < nb; b++) { int v = part[b]; part[b] = acc; acc += v; }
    }
}

__global__ void add_off_kernel(int* __restrict__ rowptr, int* __restrict__ cursor,
                               const int* __restrict__ part, int M) {
    int i = blockIdx.x * blockDim.x + threadIdx.x;
    if (i < M) {
        int v = rowptr[i] + part[i / SCAN_BS];
        rowptr[i] = v;
        cursor[i] = v;
    }
}

// cursor ends at rowptr[d] + deg[d] == segment end (used by gather)
__global__ void fill_kernel(const int* __restrict__ src, const int* __restrict__ dst,
                            int* __restrict__ cursor, int* __restrict__ csr, int E) {
    int e = blockIdx.x * blockDim.x + threadIdx.x;
    if (e < E) {
        int d   = __ldg(dst + e);
        int pos = atomicAdd(cursor + d, 1);
        csr[pos] = __ldg(src + e);
    }
}

// ---------------------------------------------------------------------------
// gather: one warp per dst node; agg[d] = h[d] + sum of neighbor rows
// ---------------------------------------------------------------------------
__global__ void gather_kernel(const float* __restrict__ h,
                              const int* __restrict__ rowptr,
                              const int* __restrict__ seg_end,
                              const int* __restrict__ csr,
                              float* __restrict__ agg, int M) {
    int idx  = blockIdx.x * blockDim.x + threadIdx.x;
    int node = idx >> 5;
    int lane = idx & 31;
    if (node >= M) return;
    int start = __ldg(rowptr + node);
    int end   = __ldg(seg_end + node);
    float4 sum = __ldg(((const float4*)(h + (size_t)node * DIMF)) + lane);
    for (int i = start; i < end; i++) {
        int s = __ldg(csr + i);
        float4 v = __ldg(((const float4*)(h + (size_t)s * DIMF)) + lane);
        sum.x += v.x; sum.y += v.y; sum.z += v.z; sum.w += v.w;
    }
    ((float4*)(agg + (size_t)node * DIMF))[lane] = sum;
}

// ---------------------------------------------------------------------------
// global_add_pool: one warp per node, reduce into out[batch[node]]
// ---------------------------------------------------------------------------
__global__ void zero_kernel(float4* __restrict__ p, int n4) {
    int i = blockIdx.x * blockDim.x + threadIdx.x;
    if (i < n4) p[i] = make_float4(0.f, 0.f, 0.f, 0.f);
}

__global__ void pool_kernel(const float* __restrict__ h,
                            const int* __restrict__ batch,
                            float* __restrict__ out, int M) {
    int idx  = blockIdx.x * blockDim.x + threadIdx.x;
    int node = idx >> 5;
    int lane = idx & 31;
    if (node >= M) return;
    int g = __ldg(batch + node);
    float4 v = __ldg(((const float4*)(h + (size_t)node * DIMF)) + lane);
    red_add_v4(out + (size_t)g * DIMF + lane * 4, v);
}

// ---------------------------------------------------------------------------
// C = relu(A @ W + b), fp32 via packed f32x2 FFMA.
// Block 128x128, 256 threads. Thread cols (ull units): 2tx + 16jj + {0,1},
// jj=0..3 -> all W reads are LDS.128, warp = 8x16B contiguous = 1 phase.
// A staged as dup (a,a) pairs, [k][row], stride 130 (16B-aligned rows) ->
// a reads are 2x LDS.128 broadcast. 6 LDS/k/thread vs 32 FFMA2 -> FMA-bound.
// ---------------------------------------------------------------------------
#define SA_STRIDE 130
__global__ __launch_bounds__(256, 2)
void gemm_bias_relu(const float* __restrict__ A, const float* __restrict__ W,
                    const float* __restrict__ bias, float* __restrict__ C, int M) {
    extern __shared__ char smem_raw[];
    float* sW = (float*)smem_raw;                       // [128][128] floats
    ull*   sA = (ull*)(smem_raw + DIMF * DIMF * 4);     // [32][SA_STRIDE] dup pairs

    const int tid = threadIdx.x;
    const int tx  = tid & 7;     // col phase: ull cols 2tx+16jj+p
    const int ty  = tid >> 3;    // row group: rows [4*ty, 4*ty+4)
    const int ty4 = ty * 4;
    const int row0 = blockIdx.x * 128;

    // Load W: 16384 floats = 4096 float4, 256 threads x 16
    {
        const float4* Wg  = (const float4*)W;
        float4*       Ws4 = (float4*)sW;
#pragma unroll
        for (int i = 0; i < 16; i++) Ws4[tid + i * 256] = __ldg(Wg + tid + i * 256);
    }
    const ull* sWu = (const ull*)sW;   // [128][64] ull view

    ull acc[4][8];
#pragma unroll
    for (int i = 0; i < 4; i++)
#pragma unroll
        for (int j = 0; j < 8; j++) acc[i][j] = 0ull;

#pragma unroll 1
    for (int kk = 0; kk < DIMF; kk += 32) {
        // stage A chunk: 128 rows x 32 k = 1024 float4 slots, 4 per thread
        float4 v[4];
        int rr[4], kc[4];
#pragma unroll
        for (int j = 0; j < 4; j++) {
            int s = tid + j * 256;        // 0..1023
            rr[j] = s >> 3;               // row in tile (0..127)
            kc[j] = s & 7;                // float4 index in chunk (0..7)
            int grow = row0 + rr[j];
            if (grow < M)
                v[j] = __ldg(((const float4*)(A + (size_t)grow * DIMF + kk)) + kc[j]);
            else
                v[j] = make_float4(0.f, 0.f, 0.f, 0.f);
        }
        __syncthreads();   // previous chunk fully consumed
#pragma unroll
        for (int j = 0; j < 4; j++) {
            int kb = kc[j] * 4;
            sA[(kb + 0) * SA_STRIDE + rr[j]] = dup_f(v[j].x);
            sA[(kb + 1) * SA_STRIDE + rr[j]] = dup_f(v[j].y);
            sA[(kb + 2) * SA_STRIDE + rr[j]] = dup_f(v[j].z);
            sA[(kb + 3) * SA_STRIDE + rr[j]] = dup_f(v[j].w);
        }
        __syncthreads();

#pragma unroll 4
        for (int k = 0; k < 32; k++) {
            ulonglong2 a01 = *(const ulonglong2*)(sA + k * SA_STRIDE + ty4);
            ulonglong2 a23 = *(const ulonglong2*)(sA + k * SA_STRIDE + ty4 + 2);
            ull a[4];
            a[0] = a01.x; a[1] = a01.y; a[2] = a23.x; a[3] = a23.y;
            ull b[8];
#pragma unroll
            for (int jj = 0; jj < 4; jj++) {
                ulonglong2 bb = *(const ulonglong2*)(sWu + (kk + k) * 64 + 2 * tx + 16 * jj);
                b[2 * jj]     = bb.x;
                b[2 * jj + 1] = bb.y;
            }
#pragma unroll
            for (int i = 0; i < 4; i++)
#pragma unroll
                for (int j = 0; j < 8; j++)
                    acc[i][j] = ffma2(a[i], b[j], acc[i][j]);
        }
    }

    // epilogue: + bias, relu, STG.128 per (row, col-quad)
    const ull* bu = (const ull*)bias;
    ull bv[8];
#pragma unroll
    for (int jj = 0; jj < 4; jj++) {
#pragma unroll
        for (int p = 0; p < 2; p++)
            bv[2 * jj + p] = __ldg(bu + 2 * tx + 16 * jj + p);
    }

#pragma unroll
    for (int i = 0; i < 4; i++) {
        int row = row0 + ty4 + i;
        if (row < M) {
            ull* cp = (ull*)(C + (size_t)row * DIMF);
#pragma unroll
            for (int jj = 0; jj < 4; jj++) {
                ulonglong2 o;
                {
                    ull ac = acc[i][2 * jj], bb = bv[2 * jj];
                    o.x = pack2(fmaxf(lo_f(ac) + lo_f(bb), 0.f),
                                fmaxf(hi_f(ac) + hi_f(bb), 0.f));
                }
                {
                    ull ac = acc[i][2 * jj + 1], bb = bv[2 * jj + 1];
                    o.y = pack2(fmaxf(lo_f(ac) + lo_f(bb), 0.f),
                                fmaxf(hi_f(ac) + hi_f(bb), 0.f));
                }
                *(ulonglong2*)(cp + 2 * tx + 16 * jj) = o;
            }
        }
    }
}

// ---------------------------------------------------------------------------
// launch
// ---------------------------------------------------------------------------
extern "C" void kernel_launch(void* const* d_in, const int* in_sizes, int n_in,
                              void* d_out, int out_size) {
    const float* x     = (const float*)d_in[0];
    const int*   ei    = (const int*)d_in[1];
    const int*   batch = (const int*)d_in[2];
    const int E = in_sizes[1] / 2;
    const int M = in_sizes[2];          // number of nodes
    const int* src = ei;
    const int* dst = ei + E;

    void *p_agg, *p_tmp, *p_h, *p_deg, *p_rp, *p_cur, *p_csr, *p_part;
    cudaGetSymbolAddress(&p_agg,  g_agg);
    cudaGetSymbolAddress(&p_tmp,  g_tmp);
    cudaGetSymbolAddress(&p_h,    g_h);
    cudaGetSymbolAddress(&p_deg,  g_deg);
    cudaGetSymbolAddress(&p_rp,   g_rowptr);
    cudaGetSymbolAddress(&p_cur,  g_cursor);
    cudaGetSymbolAddress(&p_csr,  g_csr);
    cudaGetSymbolAddress(&p_part, g_part);
    float* agg = (float*)p_agg;
    float* tmp = (float*)p_tmp;
    float* hbf = (float*)p_h;
    int* deg    = (int*)p_deg;
    int* rowptr = (int*)p_rp;
    int* cursor = (int*)p_cur;
    int* csr    = (int*)p_csr;
    int* part   = (int*)p_part;

    const int SMEM_GEMM = DIMF * DIMF * 4 + 32 * SA_STRIDE * 8;   // ~96.5 KB
    cudaFuncSetAttribute(gemm_bias_relu,
                         cudaFuncAttributeMaxDynamicSharedMemorySize, SMEM_GEMM);

    const int nb       = (M + SCAN_BS - 1) / SCAN_BS;
    const int eBlocks  = (E + 255) / 256;
    const int mBlocks  = (M + 255) / 256;
    const int gaBlocks = (M * 32 + 255) / 256;
    const int poBlocks = (M * 32 + 255) / 256;
    const int gmBlocks = (M + 127) / 128;

    // ---- CSR build (once; reused by all 3 layers) ----
    zero_int_kernel<<<mBlocks, 256>>>(deg, M);
    hist_kernel<<<eBlocks, 256>>>(dst, deg, E);
    scan_block_kernel<<<nb, SCAN_BS>>>(deg, rowptr, part, M);
    scan_part_kernel<<<1, 32>>>(part, nb);
    add_off_kernel<<<mBlocks, 256>>>(rowptr, cursor, part, M);
    fill_kernel<<<eBlocks, 256>>>(src, dst, cursor, csr, E);
    // cursor[d] now == segment end for node d

    const float* h = x;
    for (int l = 0; l < 3; l++) {
        const float* W1 = (const float*)d_in[3 + 4 * l + 0];
        const float* b1 = (const float*)d_in[3 + 4 * l + 1];
        const float* W2 = (const float*)d_in[3 + 4 * l + 2];
        const float* b2 = (const float*)d_in[3 + 4 * l + 3];

        gather_kernel<<<gaBlocks, 256>>>(h, rowptr, cursor, csr, agg, M);
        gemm_bias_relu<<<gmBlocks, 256, SMEM_GEMM>>>(agg, W1, b1, tmp, M);
        gemm_bias_relu<<<gmBlocks, 256, SMEM_GEMM>>>(tmp, W2, b2, hbf, M);
        h = hbf;
    }

    zero_kernel<<<(out_size / 4 + 255) / 256, 256>>>((float4*)d_out, out_size / 4);
    pool_kernel<<<poBlocks, 256>>>(h, batch, (float*)d_out, M);
}

// round 6
// speedup vs baseline: 2.9766x; 1.5034x over previous
#include <cuda_runtime.h>
#include <cuda_bf16.h>

// ============================================================================
// LigandEncoder (3-layer GIN + global_add_pool)
//   CSR gather aggregation + bf16-split (3-pass) mma.sync tensor-core GEMMs
// ============================================================================

#define DIMF 128
typedef unsigned long long ull;

#define MAXN 100000
#define MAXE 1600000
#define SCAN_BS 1024

// Scratch (allocation-free rule: __device__ globals).
__device__ float g_agg[(size_t)MAXN * DIMF];
__device__ float g_tmp[(size_t)MAXN * DIMF];
__device__ float g_h  [(size_t)MAXN * DIMF];
__device__ int   g_deg[MAXN];
__device__ int   g_rowptr[MAXN];
__device__ int   g_cursor[MAXN];
__device__ int   g_csr[MAXE];
__device__ int   g_part[(MAXN + SCAN_BS - 1) / SCAN_BS + 1];
// per weight w: hi image 8192 b32 + lo image 8192 b32 (fragment-ordered)
__device__ __nv_bfloat16 g_wimg[6 * 32768];

// ---------------------------------------------------------------------------
// helpers
// ---------------------------------------------------------------------------
__device__ __forceinline__ unsigned smem_u32(const void* p) {
    unsigned a;
    asm("{ .reg .u64 t; cvta.to.shared.u64 t, %1; cvt.u32.u64 %0, t; }"
        : "=r"(a) : "l"(p));
    return a;
}
__device__ __forceinline__ unsigned bf2(__nv_bfloat16 a, __nv_bfloat16 b) {
    unsigned short ua = __bfloat16_as_ushort(a), ub = __bfloat16_as_ushort(b);
    return ((unsigned)ub << 16) | ua;
}
__device__ __forceinline__ ull pack2(float lo, float hi) {
    return ((ull)__float_as_uint(hi) << 32) | (ull)__float_as_uint(lo);
}
__device__ __forceinline__ void split4(float4 v, ull& hi, ull& lo) {
    __nv_bfloat16 h0 = __float2bfloat16_rn(v.x), h1 = __float2bfloat16_rn(v.y);
    __nv_bfloat16 h2 = __float2bfloat16_rn(v.z), h3 = __float2bfloat16_rn(v.w);
    __nv_bfloat16 l0 = __float2bfloat16_rn(v.x - __bfloat162float(h0));
    __nv_bfloat16 l1 = __float2bfloat16_rn(v.y - __bfloat162float(h1));
    __nv_bfloat16 l2 = __float2bfloat16_rn(v.z - __bfloat162float(h2));
    __nv_bfloat16 l3 = __float2bfloat16_rn(v.w - __bfloat162float(h3));
    hi = ((ull)bf2(h2, h3) << 32) | bf2(h0, h1);
    lo = ((ull)bf2(l2, l3) << 32) | bf2(l0, l1);
}
__device__ __forceinline__ void red_add_v4(const float* p, float4 v) {
    asm volatile("red.global.add.v4.f32 [%0], {%1,%2,%3,%4};"
                 :: "l"(p), "f"(v.x), "f"(v.y), "f"(v.z), "f"(v.w)
                 : "memory");
}
__device__ __forceinline__ void ldmatrix_x4(unsigned* f, unsigned addr) {
    asm volatile("ldmatrix.sync.aligned.m8n8.x4.shared.b16 {%0,%1,%2,%3}, [%4];"
                 : "=r"(f[0]), "=r"(f[1]), "=r"(f[2]), "=r"(f[3]) : "r"(addr));
}
__device__ __forceinline__ void lds_v2(unsigned& b0, unsigned& b1, unsigned addr) {
    asm volatile("ld.shared.v2.b32 {%0,%1}, [%2];" : "=r"(b0), "=r"(b1) : "r"(addr));
}
__device__ __forceinline__ void mma16816(float* c, const unsigned* a,
                                         unsigned b0, unsigned b1) {
    asm volatile(
        "mma.sync.aligned.m16n8k16.row.col.f32.bf16.bf16.f32 "
        "{%0,%1,%2,%3}, {%4,%5,%6,%7}, {%8,%9}, {%0,%1,%2,%3};"
        : "+f"(c[0]), "+f"(c[1]), "+f"(c[2]), "+f"(c[3])
        : "r"(a[0]), "r"(a[1]), "r"(a[2]), "r"(a[3]), "r"(b0), "r"(b1));
}

// ---------------------------------------------------------------------------
// W prep: fp32 W[k][n] -> fragment-ordered bf16 hi/lo images.
// Image b32 index: (kt*16 + nt)*64 + lane*2 + half,
//   half 0 -> b0: elems (k = kt*16 + (lane%4)*2 + {0,1}, n = nt*8 + lane/4)
//   half 1 -> b1: k += 8
// ---------------------------------------------------------------------------
__global__ void wprep_kernel(const float* W0, const float* W1, const float* W2,
                             const float* W3, const float* W4, const float* W5,
                             __nv_bfloat16* out) {
    int w = blockIdx.x >> 3;
    const float* W = (w == 0) ? W0 : (w == 1) ? W1 : (w == 2) ? W2
                    : (w == 3) ? W3 : (w == 4) ? W4 : W5;
    unsigned* hi_img = (unsigned*)(out + (size_t)w * 32768);
    unsigned* lo_img = hi_img + 8192;

    int seg = blockIdx.x & 7;
#pragma unroll
    for (int it = 0; it < 4; it++) {
        int idx    = seg * 1024 + it * 256 + threadIdx.x;   // 0..8191
        int tile   = idx >> 6;
        int within = idx & 63;
        int lane   = within >> 1;
        int half   = within & 1;
        int kt = tile >> 4, nt = tile & 15;
        int k = kt * 16 + half * 8 + (lane & 3) * 2;
        int n = nt * 8 + (lane >> 2);
        float w0 = __ldg(W + (size_t)k * 128 + n);
        float w1 = __ldg(W + (size_t)(k + 1) * 128 + n);
        __nv_bfloat16 h0 = __float2bfloat16_rn(w0), h1 = __float2bfloat16_rn(w1);
        __nv_bfloat16 l0 = __float2bfloat16_rn(w0 - __bfloat162float(h0));
        __nv_bfloat16 l1 = __float2bfloat16_rn(w1 - __bfloat162float(h1));
        hi_img[idx] = bf2(h0, h1);
        lo_img[idx] = bf2(l0, l1);
    }
}

// ---------------------------------------------------------------------------
// Tensor-core GEMM: C = relu(A @ W + b), A (M,128) fp32, W as hi/lo images.
// Block 128 rows x 128 cols, 512 threads = 16 warps (4 row x 4 col),
// warp tile 32x32 via m16n8k16 (2 mtiles x 4 ntiles). 3 split passes.
// A smem: hi/lo, row pitch 272B (68 banks == 4 mod 32 -> ldmatrix conflict-free).
// ---------------------------------------------------------------------------
#define A_PITCH 272u
#define SM_A_HI 0u
#define SM_A_LO (128u * A_PITCH)               // 34816
#define SM_B_HI (2u * 128u * A_PITCH)          // 69632
#define SM_B_LO (SM_B_HI + 32768u)             // 102400
#define SMEM_MM (SM_B_LO + 32768u)             // 135168

__global__ __launch_bounds__(512, 1)
void gemm_mma(const float* __restrict__ A, const __nv_bfloat16* __restrict__ wimg,
              const float* __restrict__ bias, float* __restrict__ C, int M) {
    extern __shared__ char smem[];
    const unsigned sb = smem_u32(smem);
    const int tid  = threadIdx.x;
    const int lane = tid & 31;
    const int wid  = tid >> 5;
    const int wm   = wid & 3;       // row group: rows [32*wm, 32*wm+32)
    const int wn   = wid >> 2;      // col group: ntiles wn*4..wn*4+3
    const int row0 = blockIdx.x * 128;

    // stage W images: 65536 B = 4096 float4
    {
        const float4* ws = (const float4*)wimg;
        float4* wd = (float4*)(smem + SM_B_HI);
#pragma unroll
        for (int i = 0; i < 8; i++) wd[tid + i * 512] = __ldg(ws + tid + i * 512);
    }
    // stage + split A: 128 rows x 32 float4
#pragma unroll
    for (int it = 0; it < 8; it++) {
        int f = it * 512 + tid;          // 0..4095
        int m = f >> 5;
        int q = f & 31;                  // float4 idx in row
        float4 v = make_float4(0.f, 0.f, 0.f, 0.f);
        if (row0 + m < M)
            v = __ldg((const float4*)(A + (size_t)(row0 + m) * DIMF + q * 4));
        ull hi, lo;
        split4(v, hi, lo);
        unsigned off = m * A_PITCH + q * 8;
        *(ull*)(smem + SM_A_HI + off) = hi;
        *(ull*)(smem + SM_A_LO + off) = lo;
    }
    __syncthreads();

    float acc[2][4][4];
#pragma unroll
    for (int i = 0; i < 2; i++)
#pragma unroll
        for (int j = 0; j < 4; j++)
#pragma unroll
            for (int q = 0; q < 4; q++) acc[i][j][q] = 0.f;

    // ldmatrix lane address components
    const int arow  = lane & 15;          // row within 16-row mtile
    const int acolb = (lane >> 4) * 16;   // byte offset of 8-col k block

#pragma unroll
    for (int pass = 0; pass < 3; pass++) {
        const unsigned ab = sb + ((pass == 2) ? SM_A_LO : SM_A_HI);
        const unsigned bb = sb + ((pass == 1) ? SM_B_LO : SM_B_HI);
#pragma unroll
        for (int kt = 0; kt < 8; kt++) {
            unsigned fa0[4], fa1[4];
            unsigned ad = ab + (wm * 32 + arow) * A_PITCH + kt * 32 + acolb;
            ldmatrix_x4(fa0, ad);
            ldmatrix_x4(fa1, ad + 16 * A_PITCH);
#pragma unroll
            for (int j = 0; j < 4; j++) {
                int nt = wn * 4 + j;
                unsigned b0, b1;
                lds_v2(b0, b1, bb + ((kt * 16 + nt) * 64 + lane * 2) * 4);
                mma16816(acc[0][j], fa0, b0, b1);
                mma16816(acc[1][j], fa1, b0, b1);
            }
        }
    }

    // epilogue: + bias, relu
#pragma unroll
    for (int j = 0; j < 4; j++) {
        int col = (wn * 4 + j) * 8 + 2 * (lane & 3);
        ull bv = __ldg((const ull*)(bias + col));
        float bx = __uint_as_float((unsigned)bv);
        float by = __uint_as_float((unsigned)(bv >> 32));
#pragma unroll
        for (int i = 0; i < 2; i++) {
            int r = row0 + wm * 32 + i * 16 + (lane >> 2);
            if (r < M) {
                *(ull*)(C + (size_t)r * DIMF + col) =
                    pack2(fmaxf(acc[i][j][0] + bx, 0.f),
                          fmaxf(acc[i][j][1] + by, 0.f));
            }
            if (r + 8 < M) {
                *(ull*)(C + (size_t)(r + 8) * DIMF + col) =
                    pack2(fmaxf(acc[i][j][2] + bx, 0.f),
                          fmaxf(acc[i][j][3] + by, 0.f));
            }
        }
    }
}

// ---------------------------------------------------------------------------
// CSR build kernels
// ---------------------------------------------------------------------------
__global__ void zero_int_kernel(int* __restrict__ p, int n) {
    int i = blockIdx.x * blockDim.x + threadIdx.x;
    if (i < n) p[i] = 0;
}

__global__ void hist_kernel(const int* __restrict__ dst, int* __restrict__ deg, int E) {
    int e = blockIdx.x * blockDim.x + threadIdx.x;
    if (e < E) atomicAdd(deg + __ldg(dst + e), 1);
}

__global__ void scan_block_kernel(const int* __restrict__ deg, int* __restrict__ rowptr,
                                  int* __restrict__ part, int M) {
    __shared__ int sh[SCAN_BS];
    int i = blockIdx.x * SCAN_BS + threadIdx.x;
    int v = (i < M) ? deg[i] : 0;
    sh[threadIdx.x] = v;
    __syncthreads();
#pragma unroll
    for (int off = 1; off < SCAN_BS; off <<= 1) {
        int t = (threadIdx.x >= off) ? sh[threadIdx.x - off] : 0;
        __syncthreads();
        sh[threadIdx.x] += t;
        __syncthreads();
    }
    if (i < M) rowptr[i] = sh[threadIdx.x] - v;   // exclusive
    if (threadIdx.x == SCAN_BS - 1) part[blockIdx.x] = sh[SCAN_BS - 1];
}

__global__ void scan_part_kernel(int* __restrict__ part, int nb) {
    __shared__ int sh[128];
    int t = threadIdx.x;
    int v = (t < nb) ? part[t] : 0;
    sh[t] = v;
    __syncthreads();
#pragma unroll
    for (int off = 1; off < 128; off <<= 1) {
        int u = (t >= off) ? sh[t - off] : 0;
        __syncthreads();
        sh[t] += u;
        __syncthreads();
    }
    if (t < nb) part[t] = sh[t] - v;
}

__global__ void add_off_kernel(int* __restrict__ rowptr, int* __restrict__ cursor,
                               const int* __restrict__ part, int M) {
    int i = blockIdx.x * blockDim.x + threadIdx.x;
    if (i < M) {
        int v = rowptr[i] + part[i / SCAN_BS];
        rowptr[i] = v;
        cursor[i] = v;
    }
}

__global__ void fill_kernel(const int* __restrict__ src, const int* __restrict__ dst,
                            int* __restrict__ cursor, int* __restrict__ csr, int E) {
    int e = blockIdx.x * blockDim.x + threadIdx.x;
    if (e < E) {
        int d   = __ldg(dst + e);
        int pos = atomicAdd(cursor + d, 1);
        csr[pos] = __ldg(src + e);
    }
}

// ---------------------------------------------------------------------------
// gather: one warp per dst node; agg[d] = h[d] + sum of neighbor rows
// ---------------------------------------------------------------------------
__global__ void gather_kernel(const float* __restrict__ h,
                              const int* __restrict__ rowptr,
                              const int* __restrict__ seg_end,
                              const int* __restrict__ csr,
                              float* __restrict__ agg, int M) {
    int idx  = blockIdx.x * blockDim.x + threadIdx.x;
    int node = idx >> 5;
    int lane = idx & 31;
    if (node >= M) return;
    int start = __ldg(rowptr + node);
    int end   = __ldg(seg_end + node);
    float4 sum = __ldg(((const float4*)(h + (size_t)node * DIMF)) + lane);
    for (int i = start; i < end; i++) {
        int s = __ldg(csr + i);
        float4 v = __ldg(((const float4*)(h + (size_t)s * DIMF)) + lane);
        sum.x += v.x; sum.y += v.y; sum.z += v.z; sum.w += v.w;
    }
    ((float4*)(agg + (size_t)node * DIMF))[lane] = sum;
}

// ---------------------------------------------------------------------------
// pooling
// ---------------------------------------------------------------------------
__global__ void zero_kernel(float4* __restrict__ p, int n4) {
    int i = blockIdx.x * blockDim.x + threadIdx.x;
    if (i < n4) p[i] = make_float4(0.f, 0.f, 0.f, 0.f);
}

__global__ void pool_kernel(const float* __restrict__ h,
                            const int* __restrict__ batch,
                            float* __restrict__ out, int M) {
    int idx  = blockIdx.x * blockDim.x + threadIdx.x;
    int node = idx >> 5;
    int lane = idx & 31;
    if (node >= M) return;
    int g = __ldg(batch + node);
    float4 v = __ldg(((const float4*)(h + (size_t)node * DIMF)) + lane);
    red_add_v4(out + (size_t)g * DIMF + lane * 4, v);
}

// ---------------------------------------------------------------------------
// launch
// ---------------------------------------------------------------------------
extern "C" void kernel_launch(void* const* d_in, const int* in_sizes, int n_in,
                              void* d_out, int out_size) {
    const float* x     = (const float*)d_in[0];
    const int*   ei    = (const int*)d_in[1];
    const int*   batch = (const int*)d_in[2];
    const int E = in_sizes[1] / 2;
    const int M = in_sizes[2];
    const int* src = ei;
    const int* dst = ei + E;

    void *p_agg, *p_tmp, *p_h, *p_deg, *p_rp, *p_cur, *p_csr, *p_part, *p_wimg;
    cudaGetSymbolAddress(&p_agg,  g_agg);
    cudaGetSymbolAddress(&p_tmp,  g_tmp);
    cudaGetSymbolAddress(&p_h,    g_h);
    cudaGetSymbolAddress(&p_deg,  g_deg);
    cudaGetSymbolAddress(&p_rp,   g_rowptr);
    cudaGetSymbolAddress(&p_cur,  g_cursor);
    cudaGetSymbolAddress(&p_csr,  g_csr);
    cudaGetSymbolAddress(&p_part, g_part);
    cudaGetSymbolAddress(&p_wimg, g_wimg);
    float* agg = (float*)p_agg;
    float* tmp = (float*)p_tmp;
    float* hbf = (float*)p_h;
    int* deg    = (int*)p_deg;
    int* rowptr = (int*)p_rp;
    int* cursor = (int*)p_cur;
    int* csr    = (int*)p_csr;
    int* part   = (int*)p_part;
    __nv_bfloat16* wimg = (__nv_bfloat16*)p_wimg;

    cudaFuncSetAttribute(gemm_mma, cudaFuncAttributeMaxDynamicSharedMemorySize, SMEM_MM);

    const int nb       = (M + SCAN_BS - 1) / SCAN_BS;
    const int eBlocks  = (E + 255) / 256;
    const int mBlocks  = (M + 255) / 256;
    const int gaBlocks = (M * 32 + 255) / 256;
    const int gmBlocks = (M + 127) / 128;

    // ---- weight prep (once; weights static across layers) ----
    wprep_kernel<<<48, 256>>>(
        (const float*)d_in[3],  (const float*)d_in[5],
        (const float*)d_in[7],  (const float*)d_in[9],
        (const float*)d_in[11], (const float*)d_in[13], wimg);

    // ---- CSR build (once) ----
    zero_int_kernel<<<mBlocks, 256>>>(deg, M);
    hist_kernel<<<eBlocks, 256>>>(dst, deg, E);
    scan_block_kernel<<<nb, SCAN_BS>>>(deg, rowptr, part, M);
    scan_part_kernel<<<1, 128>>>(part, nb);
    add_off_kernel<<<mBlocks, 256>>>(rowptr, cursor, part, M);
    fill_kernel<<<eBlocks, 256>>>(src, dst, cursor, csr, E);
    // cursor[d] now == segment end for node d

    const float* h = x;
    for (int l = 0; l < 3; l++) {
        const __nv_bfloat16* w1img = wimg + (size_t)(2 * l)     * 32768;
        const __nv_bfloat16* w2img = wimg + (size_t)(2 * l + 1) * 32768;
        const float* b1 = (const float*)d_in[3 + 4 * l + 1];
        const float* b2 = (const float*)d_in[3 + 4 * l + 3];

        gather_kernel<<<gaBlocks, 256>>>(h, rowptr, cursor, csr, agg, M);
        gemm_mma<<<gmBlocks, 512, SMEM_MM>>>(agg, w1img, b1, tmp, M);
        gemm_mma<<<gmBlocks, 512, SMEM_MM>>>(tmp, w2img, b2, hbf, M);
        h = hbf;
    }

    zero_kernel<<<(out_size / 4 + 255) / 256, 256>>>((float4*)d_out, out_size / 4);
    pool_kernel<<<gaBlocks, 256>>>(h, batch, (float*)d_out, M);
}